// round 16
// baseline (speedup 1.0000x reference)
#include <cuda_runtime.h>
#include <cuda_fp16.h>
#include <math.h>
#include <cstdint>

// ---------------------------------------------------------------------------
// Problem constants
// ---------------------------------------------------------------------------
#define BATCH 8
#define SV    257
#define SQ    2048
#define DV    1024
#define DM    2304
#define NH    8
#define DK    288
#define DF    9216
#define ROWS_T (BATCH*SQ)  // 16384
#define ROWS_V (BATCH*SV)  // 2056

// ---------------------------------------------------------------------------
// Scratch (device globals; no runtime allocation allowed)
// ---------------------------------------------------------------------------
__device__ float  g_x  [(size_t)ROWS_T * DM];
__device__ __half g_q  [(size_t)ROWS_T * DM];
__device__ __half g_kv [(size_t)ROWS_V * 2 * DM];   // fused [k|v] per row
__device__ __half g_pv [(size_t)ROWS_V * DM];
__device__ __half g_nt [(size_t)ROWS_T * DM];
__device__ __half g_ctx[(size_t)ROWS_T * DM];
__device__ __half g_h  [(size_t)ROWS_T * DF];
__device__ __half g_vis[(size_t)ROWS_V * DV];
// fp16 weight copies (WK region holds fused [2304 x 4608] kv weight)
#define OFF_VP 0
#define OFF_WQ (OFF_VP + (size_t)DV*DM)
#define OFF_WK (OFF_WQ + (size_t)DM*DM)
#define OFF_WO (OFF_WK + 2*(size_t)DM*DM)
#define OFF_F1 (OFF_WO + (size_t)DM*DM)
#define OFF_F2 (OFF_F1 + (size_t)DM*DF)
#define W16_TOTAL (OFF_F2 + (size_t)DF*DM)
__device__ __half g_w16[W16_TOTAL];

// ---------------------------------------------------------------------------
// helpers
// ---------------------------------------------------------------------------
__device__ __forceinline__ uint32_t smem_u32(const void* p) {
    uint32_t a;
    asm("{ .reg .u64 t; cvta.to.shared.u64 t, %1; cvt.u32.u64 %0, t; }"
        : "=r"(a) : "l"(p));
    return a;
}
__device__ __forceinline__ void cp16(uint32_t dst, const void* src, uint32_t n) {
    asm volatile("cp.async.cg.shared.global [%0], [%1], 16, %2;"
                 :: "r"(dst), "l"(src), "r"(n) : "memory");
}
#define CP_COMMIT() asm volatile("cp.async.commit_group;" ::: "memory")
#define CP_WAIT(N)  asm volatile("cp.async.wait_group %0;" :: "n"(N) : "memory")

__device__ __forceinline__ void ldsm_x4(uint32_t* r, uint32_t addr) {
    asm volatile("ldmatrix.sync.aligned.m8n8.x4.shared.b16 {%0,%1,%2,%3}, [%4];"
        : "=r"(r[0]), "=r"(r[1]), "=r"(r[2]), "=r"(r[3]) : "r"(addr));
}
__device__ __forceinline__ void ldsm_x4_t(uint32_t* r, uint32_t addr) {
    asm volatile("ldmatrix.sync.aligned.m8n8.x4.trans.shared.b16 {%0,%1,%2,%3}, [%4];"
        : "=r"(r[0]), "=r"(r[1]), "=r"(r[2]), "=r"(r[3]) : "r"(addr));
}
__device__ __forceinline__ void mma_f16(float* c, const uint32_t* a,
                                        const uint32_t* b) {
    asm volatile(
        "mma.sync.aligned.m16n8k16.row.col.f32.f16.f16.f32 "
        "{%0,%1,%2,%3}, {%4,%5,%6,%7}, {%8,%9}, {%0,%1,%2,%3};"
        : "+f"(c[0]), "+f"(c[1]), "+f"(c[2]), "+f"(c[3])
        : "r"(a[0]), "r"(a[1]), "r"(a[2]), "r"(a[3]), "r"(b[0]), "r"(b[1]));
}
__device__ __forceinline__ float gelu_exact(float x) {
    return 0.5f * x * (1.0f + erff(x * 0.70710678118654752f));
}
__device__ __forceinline__ uint2 pack4(float a, float b, float c, float d) {
    const __half2 h0 = __floats2half2_rn(a, b);
    const __half2 h1 = __floats2half2_rn(c, d);
    uint2 u;
    u.x = *(const unsigned int*)&h0;
    u.y = *(const unsigned int*)&h1;
    return u;
}

// ---------------------------------------------------------------------------
// conversion kernels (vectorized: 2x float4 per thread per iter for MLP)
// ---------------------------------------------------------------------------
__global__ void __launch_bounds__(256)
cvt16_kernel(const float4* __restrict__ in, uint2* __restrict__ out, size_t n4)
{
    const size_t stride = (size_t)gridDim.x * 512;
    for (size_t i0 = (size_t)blockIdx.x * 512 + threadIdx.x; i0 < n4;
         i0 += stride) {
        const size_t i1 = i0 + 256;
        const float4 v0 = in[i0];
        if (i1 < n4) {
            const float4 v1 = in[i1];
            out[i0] = pack4(v0.x, v0.y, v0.z, v0.w);
            out[i1] = pack4(v1.x, v1.y, v1.z, v1.w);
        } else {
            out[i0] = pack4(v0.x, v0.y, v0.z, v0.w);
        }
    }
}
// fused K|V weight conversion into pitch-2DM layout
__global__ void __launch_bounds__(256)
cvtkv_kernel(const float4* __restrict__ k4, const float4* __restrict__ v4,
             uint2* __restrict__ out)   // out pitch = 2*DM halfs = 1152 uint2
{
    const int n4 = DM * (DM / 4);      // 1327104
    for (int i = blockIdx.x * 256 + threadIdx.x; i < n4;
         i += gridDim.x * 256) {
        const int r = i / (DM / 4);
        const int c = i - r * (DM / 4);
        const float4 a = k4[i];
        const float4 b = v4[i];
        out[(size_t)r * (2 * DM / 4) + c]            = pack4(a.x, a.y, a.z, a.w);
        out[(size_t)r * (2 * DM / 4) + (DM / 4) + c] = pack4(b.x, b.y, b.z, b.w);
    }
}

// ---------------------------------------------------------------------------
// fp16 HMMA GEMM: C[M,N] = A[M,K] @ B[K,N] + bias (+ epilogue)
//   EPI 0: +bias   EPI 1: +bias+res   EPI 2: gelu(+bias)
//   OUT16: write __half output, else float.
//   bias2/bsplit: two-bias concat (block entirely on one side; TN | bsplit).
// CTA tile 128x128, KC=64, 3-stage cp.async, 256 thr, 8 warps x (64x32),
// __launch_bounds__(256, 2): TWO CTAs per SM so one CTA's barrier drain is
// covered by the other CTA's compute (fix for the 60%-tensor stall in R14/15).
// Requires: K % 64 == 0, N % 128 == 0, K/64 >= 2. M tail handled.
// ---------------------------------------------------------------------------
#define TM 128
#define TN 128
#define KC 64
#define NSTG 3
#define A_ROWB 144                     // 128B data + 16B pad
#define A_BYTES (128 * A_ROWB)         // 18432
#define B_BYTES (KC * 256)             // 16384 (128 fp16 per k-row)
#define STG_BYTES (A_BYTES + B_BYTES)  // 34816
#define GEMM_SMEM (NSTG * STG_BYTES)   // 104448 (x2 CTAs = 208896 <= 227KB)

__device__ __forceinline__ void load_stage(
    const __half* __restrict__ A, const __half* __restrict__ Bw,
    int M, int N, int K, uint32_t stg, int bm, int n0, int kc, int tid)
{
#pragma unroll
    for (int i = 0; i < 4; i++) {   // A: 1024 cp16 / 256 thr
        const int ai = tid + i * 256;
        const int row = ai >> 3, c = ai & 7;
        const int gr = bm + row;
        const int ok = gr < M;
        cp16(stg + row * A_ROWB + c * 16,
             A + (size_t)(ok ? gr : 0) * K + kc + c * 8, ok ? 16u : 0u);
    }
#pragma unroll
    for (int i = 0; i < 4; i++) {   // B: 1024 cp16 (64 rows x 16 chunks)
        const int bi = tid + i * 256;
        const int k = bi >> 4, cc = bi & 15;
        cp16(stg + A_BYTES + k * 256 + ((cc ^ (k & 7)) << 4),
             Bw + (size_t)(kc + k) * N + n0 + cc * 8, 16u);
    }
}

template <int EPI, int OUT16>
__global__ void __launch_bounds__(256, 2)
hgemm(const __half* __restrict__ A, const __half* __restrict__ Bw,
      const float* __restrict__ bias, const float* __restrict__ bias2,
      int bsplit, const float* __restrict__ res,
      void* __restrict__ Cv, int M, int N, int K)
{
    extern __shared__ char smem[];
    const uint32_t sb = smem_u32(smem);
    const int tid  = threadIdx.x;
    const int lane = tid & 31;
    const int wid  = tid >> 5;
    const int wm   = (wid >> 2) * 64;     // warp row offset (0, 64)
    const int wn   = (wid & 3) * 32;      // warp col offset (0..96)
    const int bm   = blockIdx.y * TM;
    const int n0   = blockIdx.x * TN;
    const int nch  = K / KC;

    const float* bp = bias;
    int coff = 0;
    if (bias2 != nullptr && n0 >= bsplit) { bp = bias2; coff = bsplit; }

    float c[4][4][4];
#pragma unroll
    for (int mt = 0; mt < 4; mt++)
#pragma unroll
        for (int nt = 0; nt < 4; nt++)
#pragma unroll
            for (int r = 0; r < 4; r++) c[mt][nt][r] = 0.f;

    // prologue: stages 0,1
    load_stage(A, Bw, M, N, K, sb, bm, n0, 0, tid);
    CP_COMMIT();
    load_stage(A, Bw, M, N, K, sb + STG_BYTES, bm, n0, KC, tid);
    CP_COMMIT();

    const int la_row = wm + (lane & 15);
    const int la_chk = lane >> 4;
    const int lb_k   = lane & 15;
    const int lb_chk = (wn >> 3) + (lane >> 4);

    for (int chunk = 0; chunk < nch; ++chunk) {
        CP_WAIT(1);
        __syncthreads();

        const int nx = chunk + 2;
        if (nx < nch)
            load_stage(A, Bw, M, N, K, sb + (nx % NSTG) * STG_BYTES,
                       bm, n0, nx * KC, tid);
        CP_COMMIT();

        const uint32_t stgA = sb + (chunk % NSTG) * STG_BYTES;
        const uint32_t stgB = stgA + A_BYTES;

#pragma unroll
        for (int kk = 0; kk < 4; kk++) {
            uint32_t a[4][4], bfr[2][4];
#pragma unroll
            for (int mt = 0; mt < 4; mt++)
                ldsm_x4(a[mt], stgA + (la_row + mt * 16) * A_ROWB +
                               (kk * 2 + la_chk) * 16);
            {
                const int k = kk * 16 + lb_k;
                const uint32_t krow = stgB + k * 256;
                const int swk = k & 7;
                ldsm_x4_t(bfr[0], krow + (((lb_chk    ) ^ swk) << 4));
                ldsm_x4_t(bfr[1], krow + (((lb_chk + 2) ^ swk) << 4));
            }
#pragma unroll
            for (int mt = 0; mt < 4; mt++)
#pragma unroll
                for (int nt = 0; nt < 4; nt++)
                    mma_f16(c[mt][nt], a[mt], &bfr[nt >> 1][(nt & 1) * 2]);
        }
    }

    // -------- epilogue --------
    const int l4 = lane >> 2;
    const int lk = lane & 3;
#pragma unroll
    for (int mt = 0; mt < 4; mt++) {
        const int rb = bm + wm + mt * 16 + l4;
#pragma unroll
        for (int hh = 0; hh < 2; hh++) {
            const int row = rb + hh * 8;
            if (row < M) {
#pragma unroll
                for (int nt = 0; nt < 4; nt++) {
                    const int col = n0 + wn + nt * 8 + lk * 2;
                    float v0 = c[mt][nt][hh * 2 + 0] + bp[col - coff];
                    float v1 = c[mt][nt][hh * 2 + 1] + bp[col - coff + 1];
                    if (EPI == 1) {
                        const float2 r2 = *(const float2*)&res[(size_t)row * N + col];
                        v0 += r2.x; v1 += r2.y;
                    } else if (EPI == 2) {
                        v0 = gelu_exact(v0); v1 = gelu_exact(v1);
                    }
                    if (OUT16) {
                        __half2* Cc = (__half2*)Cv;
                        Cc[((size_t)row * N + col) >> 1] =
                            __floats2half2_rn(v0, v1);
                    } else {
                        float* Cc = (float*)Cv;
                        *(float2*)&Cc[(size_t)row * N + col] = make_float2(v0, v1);
                    }
                }
            }
        }
    }
}

// ---------------------------------------------------------------------------
// LayerNorm over last dim (C = DM = 2304), one block per row; fp16 output.
// ---------------------------------------------------------------------------
__global__ void __launch_bounds__(256)
layernorm_kernel(const float* __restrict__ x, const float* __restrict__ w,
                 const float* __restrict__ bta, __half* __restrict__ y)
{
    const size_t base = (size_t)blockIdx.x * DM;
    const float4* x4 = (const float4*)(x + base);
    const float4* w4 = (const float4*)w;
    const float4* b4 = (const float4*)bta;
    uint2* y4 = (uint2*)(y + base);

    float s = 0.f, s2 = 0.f;
    for (int c = threadIdx.x; c < DM / 4; c += 256) {
        const float4 v = x4[c];
        s  += v.x + v.y + v.z + v.w;
        s2 += v.x * v.x + v.y * v.y + v.z * v.z + v.w * v.w;
    }
#pragma unroll
    for (int o = 16; o; o >>= 1) {
        s  += __shfl_xor_sync(0xffffffffu, s,  o);
        s2 += __shfl_xor_sync(0xffffffffu, s2, o);
    }
    __shared__ float sh[16];
    __shared__ float mv[2];
    const int wid = threadIdx.x >> 5, lane = threadIdx.x & 31;
    if (lane == 0) { sh[wid] = s; sh[8 + wid] = s2; }
    __syncthreads();
    if (threadIdx.x == 0) {
        float ts = 0.f, ts2 = 0.f;
#pragma unroll
        for (int i = 0; i < 8; i++) { ts += sh[i]; ts2 += sh[8 + i]; }
        const float mean = ts / (float)DM;
        const float var  = ts2 / (float)DM - mean * mean;
        mv[0] = mean;
        mv[1] = rsqrtf(var + 1e-5f);
    }
    __syncthreads();
    const float mean = mv[0], rstd = mv[1];
    for (int c = threadIdx.x; c < DM / 4; c += 256) {
        const float4 v = x4[c];
        const float4 ww = w4[c];
        const float4 bb = b4[c];
        y4[c] = pack4((v.x - mean) * rstd * ww.x + bb.x,
                      (v.y - mean) * rstd * ww.y + bb.y,
                      (v.z - mean) * rstd * ww.z + bb.z,
                      (v.w - mean) * rstd * ww.w + bb.w);
    }
}

// ---------------------------------------------------------------------------
// Tensor-core cross attention (unchanged — passing since R7).
// ---------------------------------------------------------------------------
#define ATQ 64
#define ACH 32
#define ANCH 10
#define ASS 320
#define ASS_STR 328
#define AQR 592
#define AHR 656
#define QS_BYTES (ATQ * AQR)
#define KVB      (ACH * AQR)
#define SS_BYTES (ATQ * ASS_STR * 4)
#define AH_BYTES (ATQ * AHR)
#define AT_SMEM  (QS_BYTES + 2*KVB + SS_BYTES + AH_BYTES)   // 201728

__device__ __forceinline__ void att_load_kv(const __half* base, int c,
                                            uint32_t buf, int tid)
{
#pragma unroll
    for (int i = 0; i < 5; i++) {
        const int idx = tid + i * 256;
        if (idx < ACH * 36) {
            const int r = idx / 36, cc = idx - r * 36;
            const int kr = c * ACH + r;
            const int ok = kr < SV;
            cp16(buf + r * AQR + cc * 16,
                 base + (size_t)(ok ? kr : 0) * (2 * DM) + cc * 8,
                 ok ? 16u : 0u);
        }
    }
    CP_COMMIT();
}

__global__ void __launch_bounds__(256, 1)
attention_kernel(const __half* __restrict__ Q, const __half* __restrict__ KV,
                 __half* __restrict__ O)
{
    extern __shared__ char smem[];
    const uint32_t sb  = smem_u32(smem);
    const uint32_t qsb = sb;
    const uint32_t kvb = sb + QS_BYTES;
    float*  ss = (float*)(smem + QS_BYTES + 2 * KVB);
    __half* ah = (__half*)(smem + QS_BYTES + 2 * KVB + SS_BYTES);
    const uint32_t ahb = kvb + 2 * KVB + SS_BYTES;

    const int q0   = blockIdx.x * ATQ;
    const int b    = blockIdx.y >> 3;
    const int h    = blockIdx.y & 7;
    const int tid  = threadIdx.x;
    const int lane = tid & 31;
    const int w    = tid >> 5;
    const float scale = 0.05892556509887896f;   // 1/sqrt(288)

    const __half* qg = Q + ((size_t)(b * SQ + q0)) * DM + h * DK;
#pragma unroll
    for (int i = 0; i < 9; i++) {
        const int idx = tid + i * 256;
        const int r = idx / 36, cc = idx - r * 36;
        cp16(qsb + r * AQR + cc * 16, qg + (size_t)r * DM + cc * 8, 16u);
    }
    CP_COMMIT();

    const __half* kg = KV + ((size_t)(b * SV)) * (2 * DM) + h * DK;
    const __half* vg = kg + DM;

    att_load_kv(kg, 0, kvb, tid);
    att_load_kv(kg, 1, kvb + KVB, tid);

    CP_WAIT(1);
    __syncthreads();

    const int m1 = (w & 3) * 16;
    const int n1 = (w >> 2) * 16;
    uint32_t qf[18][4];
    {
        const uint32_t abase = qsb + (m1 + (lane & 15)) * AQR + (lane >> 4) * 16;
#pragma unroll
        for (int ks = 0; ks < 18; ks++)
            ldsm_x4(qf[ks], abase + ks * 32);
    }

    const int l4 = lane >> 2, lk = lane & 3;

    // ================= pass 1: scores =================
    for (int c = 0; c < ANCH; c++) {
        if (c > 0) { CP_WAIT(1); __syncthreads(); }
        const uint32_t kb = kvb + (c & 1) * KVB;
        float sc[2][4];
#pragma unroll
        for (int nt = 0; nt < 2; nt++)
#pragma unroll
            for (int r = 0; r < 4; r++) sc[nt][r] = 0.f;

        const uint32_t bbase = kb + (n1 + (lane & 15)) * AQR + (lane >> 4) * 16;
#pragma unroll
        for (int ks = 0; ks < 18; ks++) {
            uint32_t bfk[4];
            ldsm_x4(bfk, bbase + ks * 32);
            uint32_t b0[2] = { bfk[0], bfk[2] };
            uint32_t b1[2] = { bfk[1], bfk[3] };
            mma_f16(sc[0], qf[ks], b0);
            mma_f16(sc[1], qf[ks], b1);
        }
#pragma unroll
        for (int nt = 0; nt < 2; nt++) {
            const int col = c * ACH + n1 + nt * 8 + lk * 2;
#pragma unroll
            for (int hh = 0; hh < 2; hh++) {
                const int row = m1 + l4 + hh * 8;
                const float v0 = sc[nt][hh * 2 + 0] * scale;
                const float v1 = sc[nt][hh * 2 + 1] * scale;
                ss[row * ASS_STR + col]     = (col     < SV) ? v0 : -1e30f;
                ss[row * ASS_STR + col + 1] = (col + 1 < SV) ? v1 : -1e30f;
            }
        }
        __syncthreads();
        if (c + 2 < ANCH) att_load_kv(kg, c + 2, kb, tid);
        else CP_COMMIT();
    }

    att_load_kv(vg, 0, kvb, tid);
    att_load_kv(vg, 1, kvb + KVB, tid);

    // ================= softmax =================
#pragma unroll
    for (int i = 0; i < 8; i++) {
        const int r = w * 8 + i;
        float mx = -1e30f;
#pragma unroll
        for (int j = 0; j < 10; j++)
            mx = fmaxf(mx, ss[r * ASS_STR + lane + j * 32]);
#pragma unroll
        for (int o = 16; o; o >>= 1)
            mx = fmaxf(mx, __shfl_xor_sync(0xffffffffu, mx, o));
        float sum = 0.f;
        float ev[10];
#pragma unroll
        for (int j = 0; j < 10; j++) {
            ev[j] = expf(ss[r * ASS_STR + lane + j * 32] - mx);
            sum += ev[j];
        }
#pragma unroll
        for (int o = 16; o; o >>= 1)
            sum += __shfl_xor_sync(0xffffffffu, sum, o);
        const float inv = 1.f / sum;
#pragma unroll
        for (int j = 0; j < 10; j++)
            ah[r * (AHR / 2) + lane + j * 32] = __float2half_rn(ev[j] * inv);
    }

    // ================= pass 2: ctx = attn @ V =================
    const int m2  = (w & 1) * 32;
    const int n0w = (w >> 1) * 72;
    float ctx[2][9][4];
#pragma unroll
    for (int mt = 0; mt < 2; mt++)
#pragma unroll
        for (int nt = 0; nt < 9; nt++)
#pragma unroll
            for (int r = 0; r < 4; r++) ctx[mt][nt][r] = 0.f;

    for (int c = 0; c < ANCH; c++) {
        CP_WAIT(1);
        __syncthreads();
        const uint32_t vb = kvb + (c & 1) * KVB;

        uint32_t af2[2][2][4];
#pragma unroll
        for (int mt = 0; mt < 2; mt++) {
            const uint32_t abase = ahb + (m2 + mt * 16 + (lane & 15)) * AHR +
                                   (lane >> 4) * 16;
            ldsm_x4(af2[mt][0], abase + (2 * c) * 32);
            ldsm_x4(af2[mt][1], abase + (2 * c) * 32 + 32);
        }
#pragma unroll
        for (int kk = 0; kk < 2; kk++) {
#pragma unroll
            for (int p = 0; p < 5; p++) {
                uint32_t bfk[4];
                const uint32_t baddr = vb + (kk * 16 + (lane & 15)) * AQR +
                                       (n0w + p * 16 + (lane >> 4) * 8) * 2;
                ldsm_x4_t(bfk, baddr);
#pragma unroll
                for (int mt = 0; mt < 2; mt++) {
                    mma_f16(ctx[mt][2 * p], af2[mt][kk], &bfk[0]);
                    if (2 * p + 1 < 9)
                        mma_f16(ctx[mt][2 * p + 1], af2[mt][kk], &bfk[2]);
                }
            }
        }
        __syncthreads();
        if (c + 2 < ANCH) att_load_kv(vg, c + 2, vb, tid);
        else CP_COMMIT();
    }

#pragma unroll
    for (int mt = 0; mt < 2; mt++) {
#pragma unroll
        for (int hh = 0; hh < 2; hh++) {
            const int row = m2 + mt * 16 + l4 + hh * 8;
            __half* og = O + ((size_t)(b * SQ + q0 + row)) * DM + h * DK;
#pragma unroll
            for (int nt = 0; nt < 9; nt++) {
                const int col = n0w + nt * 8 + lk * 2;
                *(__half2*)(og + col) =
                    __floats2half2_rn(ctx[mt][nt][hh * 2 + 0],
                                      ctx[mt][nt][hh * 2 + 1]);
            }
        }
    }
}

// ---------------------------------------------------------------------------
// Orchestration (single stream — graph-safe, allocation-free)
// 4th launch = Q-GEMM (the ncu-profiled slot).
// ---------------------------------------------------------------------------
extern "C" void kernel_launch(void* const* d_in, const int* in_sizes, int n_in,
                              void* d_out, int out_size)
{
    const float* vision = (const float*)d_in[0];
    const float* text   = (const float*)d_in[1];
    const float* vp_w   = (const float*)d_in[2];
    const float* vp_b   = (const float*)d_in[3];
    const float* ln1_w  = (const float*)d_in[4];
    const float* ln1_b  = (const float*)d_in[5];
    const float* ln2_w  = (const float*)d_in[6];
    const float* ln2_b  = (const float*)d_in[7];
    const float* wq_w   = (const float*)d_in[8];
    const float* wq_b   = (const float*)d_in[9];
    const float* wk_w   = (const float*)d_in[10];
    const float* wk_b   = (const float*)d_in[11];
    const float* wv_w   = (const float*)d_in[12];
    const float* wv_b   = (const float*)d_in[13];
    const float* wo_w   = (const float*)d_in[14];
    const float* wo_b   = (const float*)d_in[15];
    const float* f1_w   = (const float*)d_in[16];
    const float* f1_b   = (const float*)d_in[17];
    const float* f2_w   = (const float*)d_in[18];
    const float* f2_b   = (const float*)d_in[19];
    float* out = (float*)d_out;

    float *x;
    __half *q, *kv, *pv, *nt, *ctx, *h, *vis, *w16;
    cudaGetSymbolAddress((void**)&x,   g_x);
    cudaGetSymbolAddress((void**)&q,   g_q);
    cudaGetSymbolAddress((void**)&kv,  g_kv);
    cudaGetSymbolAddress((void**)&pv,  g_pv);
    cudaGetSymbolAddress((void**)&nt,  g_nt);
    cudaGetSymbolAddress((void**)&ctx, g_ctx);
    cudaGetSymbolAddress((void**)&h,   g_h);
    cudaGetSymbolAddress((void**)&vis, g_vis);
    cudaGetSymbolAddress((void**)&w16, g_w16);

    cudaFuncSetAttribute(hgemm<0,1>, cudaFuncAttributeMaxDynamicSharedMemorySize, GEMM_SMEM);
    cudaFuncSetAttribute(hgemm<1,0>, cudaFuncAttributeMaxDynamicSharedMemorySize, GEMM_SMEM);
    cudaFuncSetAttribute(hgemm<2,1>, cudaFuncAttributeMaxDynamicSharedMemorySize, GEMM_SMEM);
    cudaFuncSetAttribute(attention_kernel,
                         cudaFuncAttributeMaxDynamicSharedMemorySize, AT_SMEM);

    const dim3 blk(256);
    const int mtV = (ROWS_V + TM - 1) / TM;   // 17
    const int mtT = ROWS_T / TM;              // 128

    // 1. cvt wq  2. LN1  3. cvt vision  4. Q-GEMM (profiled)
    cvt16_kernel<<<2048, 256>>>((const float4*)wq_w, (uint2*)(w16 + OFF_WQ),
                                (size_t)DM * DM / 4);
    layernorm_kernel<<<ROWS_T, 256>>>(text, ln1_w, ln1_b, nt);
    cvt16_kernel<<<2048, 256>>>((const float4*)vision, (uint2*)vis,
                                (size_t)ROWS_V * DV / 4);
    hgemm<0,1><<<dim3(DM / TN, mtT), blk, GEMM_SMEM>>>(
        nt, w16 + OFF_WQ, wq_b, nullptr, 0, nullptr, q, ROWS_T, DM, DM);
    cvt16_kernel<<<2048, 256>>>((const float4*)vp_w, (uint2*)(w16 + OFF_VP),
                                (size_t)DV * DM / 4);
    hgemm<0,1><<<dim3(DM / TN, mtV), blk, GEMM_SMEM>>>(
        vis, w16 + OFF_VP, vp_b, nullptr, 0, nullptr, pv, ROWS_V, DM, DV);
    cvtkv_kernel<<<2048, 256>>>((const float4*)wk_w, (const float4*)wv_w,
                                (uint2*)(w16 + OFF_WK));
    hgemm<0,1><<<dim3((2 * DM) / TN, mtV), blk, GEMM_SMEM>>>(
        pv, w16 + OFF_WK, wk_b, wv_b, DM, nullptr, kv, ROWS_V, 2 * DM, DM);
    attention_kernel<<<dim3(SQ / ATQ, BATCH * NH), 256, AT_SMEM>>>(q, kv, ctx);
    cvt16_kernel<<<2048, 256>>>((const float4*)wo_w, (uint2*)(w16 + OFF_WO),
                                (size_t)DM * DM / 4);
    hgemm<1,0><<<dim3(DM / TN, mtT), blk, GEMM_SMEM>>>(
        ctx, w16 + OFF_WO, wo_b, nullptr, 0, text, x, ROWS_T, DM, DM);
    layernorm_kernel<<<ROWS_T, 256>>>(x, ln2_w, ln2_b, nt);
    cvt16_kernel<<<2048, 256>>>((const float4*)f1_w, (uint2*)(w16 + OFF_F1),
                                (size_t)DM * DF / 4);
    hgemm<2,1><<<dim3(DF / TN, mtT), blk, GEMM_SMEM>>>(
        nt, w16 + OFF_F1, f1_b, nullptr, 0, nullptr, h, ROWS_T, DF, DM);
    cvt16_kernel<<<2048, 256>>>((const float4*)f2_w, (uint2*)(w16 + OFF_F2),
                                (size_t)DF * DM / 4);
    hgemm<1,0><<<dim3(DM / TN, mtT), blk, GEMM_SMEM>>>(
        h, w16 + OFF_F2, f2_b, nullptr, 0, x, out, ROWS_T, DM, DF);
}

// round 17
// speedup vs baseline: 1.2454x; 1.2454x over previous
#include <cuda_runtime.h>
#include <cuda_fp16.h>
#include <math.h>
#include <cstdint>

// ---------------------------------------------------------------------------
// Problem constants
// ---------------------------------------------------------------------------
#define BATCH 8
#define SV    257
#define SQ    2048
#define DV    1024
#define DM    2304
#define NH    8
#define DK    288
#define DF    9216
#define ROWS_T (BATCH*SQ)  // 16384
#define ROWS_V (BATCH*SV)  // 2056

// ---------------------------------------------------------------------------
// Scratch (device globals; no runtime allocation allowed)
// ---------------------------------------------------------------------------
__device__ float  g_x  [(size_t)ROWS_T * DM];
__device__ __half g_q  [(size_t)ROWS_T * DM];
__device__ __half g_kv [(size_t)ROWS_V * 2 * DM];   // fused [k|v] per row
__device__ __half g_pv [(size_t)ROWS_V * DM];
__device__ __half g_nt [(size_t)ROWS_T * DM];
__device__ __half g_ctx[(size_t)ROWS_T * DM];
__device__ __half g_h  [(size_t)ROWS_T * DF];
__device__ __half g_vis[(size_t)ROWS_V * DV];
// fp16 weight copies (WK region holds fused [2304 x 4608] kv weight)
#define OFF_VP 0
#define OFF_WQ (OFF_VP + (size_t)DV*DM)
#define OFF_WK (OFF_WQ + (size_t)DM*DM)
#define OFF_WO (OFF_WK + 2*(size_t)DM*DM)
#define OFF_F1 (OFF_WO + (size_t)DM*DM)
#define OFF_F2 (OFF_F1 + (size_t)DM*DF)
#define W16_TOTAL (OFF_F2 + (size_t)DF*DM)
__device__ __half g_w16[W16_TOTAL];

// ---------------------------------------------------------------------------
// helpers
// ---------------------------------------------------------------------------
__device__ __forceinline__ uint32_t smem_u32(const void* p) {
    uint32_t a;
    asm("{ .reg .u64 t; cvta.to.shared.u64 t, %1; cvt.u32.u64 %0, t; }"
        : "=r"(a) : "l"(p));
    return a;
}
__device__ __forceinline__ void cp16(uint32_t dst, const void* src, uint32_t n) {
    asm volatile("cp.async.cg.shared.global [%0], [%1], 16, %2;"
                 :: "r"(dst), "l"(src), "r"(n) : "memory");
}
#define CP_COMMIT() asm volatile("cp.async.commit_group;" ::: "memory")
#define CP_WAIT(N)  asm volatile("cp.async.wait_group %0;" :: "n"(N) : "memory")

__device__ __forceinline__ void ldsm_x4(uint32_t* r, uint32_t addr) {
    asm volatile("ldmatrix.sync.aligned.m8n8.x4.shared.b16 {%0,%1,%2,%3}, [%4];"
        : "=r"(r[0]), "=r"(r[1]), "=r"(r[2]), "=r"(r[3]) : "r"(addr));
}
__device__ __forceinline__ void ldsm_x4_t(uint32_t* r, uint32_t addr) {
    asm volatile("ldmatrix.sync.aligned.m8n8.x4.trans.shared.b16 {%0,%1,%2,%3}, [%4];"
        : "=r"(r[0]), "=r"(r[1]), "=r"(r[2]), "=r"(r[3]) : "r"(addr));
}
__device__ __forceinline__ void mma_f16(float* c, const uint32_t* a,
                                        const uint32_t* b) {
    asm volatile(
        "mma.sync.aligned.m16n8k16.row.col.f32.f16.f16.f32 "
        "{%0,%1,%2,%3}, {%4,%5,%6,%7}, {%8,%9}, {%0,%1,%2,%3};"
        : "+f"(c[0]), "+f"(c[1]), "+f"(c[2]), "+f"(c[3])
        : "r"(a[0]), "r"(a[1]), "r"(a[2]), "r"(a[3]), "r"(b[0]), "r"(b[1]));
}
__device__ __forceinline__ float gelu_exact(float x) {
    return 0.5f * x * (1.0f + erff(x * 0.70710678118654752f));
}
__device__ __forceinline__ uint2 pack4(float a, float b, float c, float d) {
    const __half2 h0 = __floats2half2_rn(a, b);
    const __half2 h1 = __floats2half2_rn(c, d);
    uint2 u;
    u.x = *(const unsigned int*)&h0;
    u.y = *(const unsigned int*)&h1;
    return u;
}

// ---------------------------------------------------------------------------
// conversion kernels (vectorized: 2x float4 per thread per iter for MLP)
// ---------------------------------------------------------------------------
__global__ void __launch_bounds__(256)
cvt16_kernel(const float4* __restrict__ in, uint2* __restrict__ out, size_t n4)
{
    const size_t stride = (size_t)gridDim.x * 512;
    for (size_t i0 = (size_t)blockIdx.x * 512 + threadIdx.x; i0 < n4;
         i0 += stride) {
        const size_t i1 = i0 + 256;
        const float4 v0 = in[i0];
        if (i1 < n4) {
            const float4 v1 = in[i1];
            out[i0] = pack4(v0.x, v0.y, v0.z, v0.w);
            out[i1] = pack4(v1.x, v1.y, v1.z, v1.w);
        } else {
            out[i0] = pack4(v0.x, v0.y, v0.z, v0.w);
        }
    }
}
// fused K|V weight conversion into pitch-2DM layout (MLP-2: k and v loads
// issued back-to-back per iteration)
__global__ void __launch_bounds__(256)
cvtkv_kernel(const float4* __restrict__ k4, const float4* __restrict__ v4,
             uint2* __restrict__ out)   // out pitch = 2*DM halfs = 1152 uint2
{
    const int n4 = DM * (DM / 4);      // 1327104
    for (int i = blockIdx.x * 256 + threadIdx.x; i < n4;
         i += gridDim.x * 256) {
        const float4 a = k4[i];
        const float4 b = v4[i];
        const int r = i / (DM / 4);
        const int c = i - r * (DM / 4);
        out[(size_t)r * (2 * DM / 4) + c]            = pack4(a.x, a.y, a.z, a.w);
        out[(size_t)r * (2 * DM / 4) + (DM / 4) + c] = pack4(b.x, b.y, b.z, b.w);
    }
}

// ---------------------------------------------------------------------------
// fp16 HMMA GEMM: C[M,N] = A[M,K] @ B[K,N] + bias (+ epilogue)
//   EPI 0: +bias   EPI 1: +bias+res   EPI 2: gelu(+bias)
//   OUT16: write __half output, else float.
//   bias2/bsplit: two-bias concat (block entirely on one side; TN | bsplit).
//   KCV: K-chunk size (64 or 96).
// CTA tile 128x256, 3-stage cp.async, 512 thr, 16 warps x (64x32).
// (R15 configuration — measured fastest across R10-R16.)
// Requires: K % KCV == 0, N % 256 == 0, K/KCV >= 2. M tail handled.
// ---------------------------------------------------------------------------
#define TM 128
#define TN 256
#define NSTG 3

template <int KCV>
struct GC {
    static constexpr int A_ROWB = KCV * 2 + 16;          // 144 / 208
    static constexpr int A_BYTES = 128 * A_ROWB;         // 18432 / 26624
    static constexpr int B_BYTES = KCV * 512;            // 32768 / 49152
    static constexpr int STG = A_BYTES + B_BYTES;        // 51200 / 75776
    static constexpr int SMEM = NSTG * STG;              // 153600 / 227328
    static constexpr int CPR = KCV / 8;                  // A 16B-chunks per row
    static constexpr int AITER = CPR / 4;                // 2 / 3
    static constexpr int BITER = KCV / 16;               // 4 / 6
    static constexpr int KSTEPS = KCV / 16;              // 4 / 6
};

template <int KCV>
__device__ __forceinline__ void load_stage(
    const __half* __restrict__ A, const __half* __restrict__ Bw,
    int M, int N, int K, uint32_t stg, int bm, int n0, int kc, int tid)
{
    using C = GC<KCV>;
#pragma unroll
    for (int i = 0; i < C::AITER; i++) {
        const int ai = tid + i * 512;
        const int row = ai / C::CPR, c = ai % C::CPR;
        const int gr = bm + row;
        const int ok = gr < M;
        cp16(stg + row * C::A_ROWB + c * 16,
             A + (size_t)(ok ? gr : 0) * K + kc + c * 8, ok ? 16u : 0u);
    }
#pragma unroll
    for (int i = 0; i < C::BITER; i++) {
        const int bi = tid + i * 512;
        const int k = bi >> 5, cc = bi & 31;
        cp16(stg + C::A_BYTES + k * 512 + ((cc ^ (k & 7)) << 4),
             Bw + (size_t)(kc + k) * N + n0 + cc * 8, 16u);
    }
}

template <int EPI, int OUT16, int KCV>
__global__ void __launch_bounds__(512, 1)
hgemm(const __half* __restrict__ A, const __half* __restrict__ Bw,
      const float* __restrict__ bias, const float* __restrict__ bias2,
      int bsplit, const float* __restrict__ res,
      void* __restrict__ Cv, int M, int N, int K)
{
    using C = GC<KCV>;
    extern __shared__ char smem[];
    const uint32_t sb = smem_u32(smem);
    const int tid  = threadIdx.x;
    const int lane = tid & 31;
    const int wid  = tid >> 5;
    const int wm   = (wid >> 3) * 64;
    const int wn   = (wid & 7) * 32;
    const int bm   = blockIdx.y * TM;
    const int n0   = blockIdx.x * TN;
    const int nch  = K / KCV;

    const float* bp = bias;
    int coff = 0;
    if (bias2 != nullptr && n0 >= bsplit) { bp = bias2; coff = bsplit; }

    float c[4][4][4];
#pragma unroll
    for (int mt = 0; mt < 4; mt++)
#pragma unroll
        for (int nt = 0; nt < 4; nt++)
#pragma unroll
            for (int r = 0; r < 4; r++) c[mt][nt][r] = 0.f;

    // prologue: stages 0,1
    load_stage<KCV>(A, Bw, M, N, K, sb, bm, n0, 0, tid);
    CP_COMMIT();
    load_stage<KCV>(A, Bw, M, N, K, sb + C::STG, bm, n0, KCV, tid);
    CP_COMMIT();

    const int la_row = wm + (lane & 15);
    const int la_chk = lane >> 4;
    const int lb_k   = lane & 15;
    const int lb_chk = (wn >> 3) + (lane >> 4);

    for (int chunk = 0; chunk < nch; ++chunk) {
        CP_WAIT(1);
        __syncthreads();

        const int nx = chunk + 2;
        if (nx < nch)
            load_stage<KCV>(A, Bw, M, N, K, sb + (nx % NSTG) * C::STG,
                            bm, n0, nx * KCV, tid);
        CP_COMMIT();

        const uint32_t stgA = sb + (chunk % NSTG) * C::STG;
        const uint32_t stgB = stgA + C::A_BYTES;

#pragma unroll
        for (int kk = 0; kk < C::KSTEPS; kk++) {
            uint32_t a[4][4], bfr[2][4];
#pragma unroll
            for (int mt = 0; mt < 4; mt++)
                ldsm_x4(a[mt], stgA + (la_row + mt * 16) * C::A_ROWB +
                               (kk * 2 + la_chk) * 16);
            {
                const int k = kk * 16 + lb_k;
                const uint32_t krow = stgB + k * 512;
                const int swk = k & 7;
                ldsm_x4_t(bfr[0], krow + (((lb_chk    ) ^ swk) << 4));
                ldsm_x4_t(bfr[1], krow + (((lb_chk + 2) ^ swk) << 4));
            }
#pragma unroll
            for (int mt = 0; mt < 4; mt++)
#pragma unroll
                for (int nt = 0; nt < 4; nt++)
                    mma_f16(c[mt][nt], a[mt], &bfr[nt >> 1][(nt & 1) * 2]);
        }
    }

    // -------- epilogue --------
    const int l4 = lane >> 2;
    const int lk = lane & 3;
#pragma unroll
    for (int mt = 0; mt < 4; mt++) {
        const int rb = bm + wm + mt * 16 + l4;
#pragma unroll
        for (int hh = 0; hh < 2; hh++) {
            const int row = rb + hh * 8;
            if (row < M) {
#pragma unroll
                for (int nt = 0; nt < 4; nt++) {
                    const int col = n0 + wn + nt * 8 + lk * 2;
                    float v0 = c[mt][nt][hh * 2 + 0] + bp[col - coff];
                    float v1 = c[mt][nt][hh * 2 + 1] + bp[col - coff + 1];
                    if (EPI == 1) {
                        const float2 r2 = *(const float2*)&res[(size_t)row * N + col];
                        v0 += r2.x; v1 += r2.y;
                    } else if (EPI == 2) {
                        v0 = gelu_exact(v0); v1 = gelu_exact(v1);
                    }
                    if (OUT16) {
                        __half2* Cc = (__half2*)Cv;
                        Cc[((size_t)row * N + col) >> 1] =
                            __floats2half2_rn(v0, v1);
                    } else {
                        float* Cc = (float*)Cv;
                        *(float2*)&Cc[(size_t)row * N + col] = make_float2(v0, v1);
                    }
                }
            }
        }
    }
}

// ---------------------------------------------------------------------------
// LayerNorm over last dim (C = DM = 2304), one block per row; fp16 output.
// ---------------------------------------------------------------------------
__global__ void __launch_bounds__(256)
layernorm_kernel(const float* __restrict__ x, const float* __restrict__ w,
                 const float* __restrict__ bta, __half* __restrict__ y)
{
    const size_t base = (size_t)blockIdx.x * DM;
    const float4* x4 = (const float4*)(x + base);
    const float4* w4 = (const float4*)w;
    const float4* b4 = (const float4*)bta;
    uint2* y4 = (uint2*)(y + base);

    float s = 0.f, s2 = 0.f;
    for (int c = threadIdx.x; c < DM / 4; c += 256) {
        const float4 v = x4[c];
        s  += v.x + v.y + v.z + v.w;
        s2 += v.x * v.x + v.y * v.y + v.z * v.z + v.w * v.w;
    }
#pragma unroll
    for (int o = 16; o; o >>= 1) {
        s  += __shfl_xor_sync(0xffffffffu, s,  o);
        s2 += __shfl_xor_sync(0xffffffffu, s2, o);
    }
    __shared__ float sh[16];
    __shared__ float mv[2];
    const int wid = threadIdx.x >> 5, lane = threadIdx.x & 31;
    if (lane == 0) { sh[wid] = s; sh[8 + wid] = s2; }
    __syncthreads();
    if (threadIdx.x == 0) {
        float ts = 0.f, ts2 = 0.f;
#pragma unroll
        for (int i = 0; i < 8; i++) { ts += sh[i]; ts2 += sh[8 + i]; }
        const float mean = ts / (float)DM;
        const float var  = ts2 / (float)DM - mean * mean;
        mv[0] = mean;
        mv[1] = rsqrtf(var + 1e-5f);
    }
    __syncthreads();
    const float mean = mv[0], rstd = mv[1];
    for (int c = threadIdx.x; c < DM / 4; c += 256) {
        const float4 v = x4[c];
        const float4 ww = w4[c];
        const float4 bb = b4[c];
        y4[c] = pack4((v.x - mean) * rstd * ww.x + bb.x,
                      (v.y - mean) * rstd * ww.y + bb.y,
                      (v.z - mean) * rstd * ww.z + bb.z,
                      (v.w - mean) * rstd * ww.w + bb.w);
    }
}

// ---------------------------------------------------------------------------
// Tensor-core cross attention (unchanged — passing since R7).
// ---------------------------------------------------------------------------
#define ATQ 64
#define ACH 32
#define ANCH 10
#define ASS 320
#define ASS_STR 328
#define AQR 592
#define AHR 656
#define QS_BYTES (ATQ * AQR)
#define KVB      (ACH * AQR)
#define SS_BYTES (ATQ * ASS_STR * 4)
#define AH_BYTES (ATQ * AHR)
#define AT_SMEM  (QS_BYTES + 2*KVB + SS_BYTES + AH_BYTES)   // 201728

__device__ __forceinline__ void att_load_kv(const __half* base, int c,
                                            uint32_t buf, int tid)
{
#pragma unroll
    for (int i = 0; i < 5; i++) {
        const int idx = tid + i * 256;
        if (idx < ACH * 36) {
            const int r = idx / 36, cc = idx - r * 36;
            const int kr = c * ACH + r;
            const int ok = kr < SV;
            cp16(buf + r * AQR + cc * 16,
                 base + (size_t)(ok ? kr : 0) * (2 * DM) + cc * 8,
                 ok ? 16u : 0u);
        }
    }
    CP_COMMIT();
}

__global__ void __launch_bounds__(256, 1)
attention_kernel(const __half* __restrict__ Q, const __half* __restrict__ KV,
                 __half* __restrict__ O)
{
    extern __shared__ char smem[];
    const uint32_t sb  = smem_u32(smem);
    const uint32_t qsb = sb;
    const uint32_t kvb = sb + QS_BYTES;
    float*  ss = (float*)(smem + QS_BYTES + 2 * KVB);
    __half* ah = (__half*)(smem + QS_BYTES + 2 * KVB + SS_BYTES);
    const uint32_t ahb = kvb + 2 * KVB + SS_BYTES;

    const int q0   = blockIdx.x * ATQ;
    const int b    = blockIdx.y >> 3;
    const int h    = blockIdx.y & 7;
    const int tid  = threadIdx.x;
    const int lane = tid & 31;
    const int w    = tid >> 5;
    const float scale = 0.05892556509887896f;   // 1/sqrt(288)

    const __half* qg = Q + ((size_t)(b * SQ + q0)) * DM + h * DK;
#pragma unroll
    for (int i = 0; i < 9; i++) {
        const int idx = tid + i * 256;
        const int r = idx / 36, cc = idx - r * 36;
        cp16(qsb + r * AQR + cc * 16, qg + (size_t)r * DM + cc * 8, 16u);
    }
    CP_COMMIT();

    const __half* kg = KV + ((size_t)(b * SV)) * (2 * DM) + h * DK;
    const __half* vg = kg + DM;

    att_load_kv(kg, 0, kvb, tid);
    att_load_kv(kg, 1, kvb + KVB, tid);

    CP_WAIT(1);
    __syncthreads();

    const int m1 = (w & 3) * 16;
    const int n1 = (w >> 2) * 16;
    uint32_t qf[18][4];
    {
        const uint32_t abase = qsb + (m1 + (lane & 15)) * AQR + (lane >> 4) * 16;
#pragma unroll
        for (int ks = 0; ks < 18; ks++)
            ldsm_x4(qf[ks], abase + ks * 32);
    }

    const int l4 = lane >> 2, lk = lane & 3;

    // ================= pass 1: scores =================
    for (int c = 0; c < ANCH; c++) {
        if (c > 0) { CP_WAIT(1); __syncthreads(); }
        const uint32_t kb = kvb + (c & 1) * KVB;
        float sc[2][4];
#pragma unroll
        for (int nt = 0; nt < 2; nt++)
#pragma unroll
            for (int r = 0; r < 4; r++) sc[nt][r] = 0.f;

        const uint32_t bbase = kb + (n1 + (lane & 15)) * AQR + (lane >> 4) * 16;
#pragma unroll
        for (int ks = 0; ks < 18; ks++) {
            uint32_t bfk[4];
            ldsm_x4(bfk, bbase + ks * 32);
            uint32_t b0[2] = { bfk[0], bfk[2] };
            uint32_t b1[2] = { bfk[1], bfk[3] };
            mma_f16(sc[0], qf[ks], b0);
            mma_f16(sc[1], qf[ks], b1);
        }
#pragma unroll
        for (int nt = 0; nt < 2; nt++) {
            const int col = c * ACH + n1 + nt * 8 + lk * 2;
#pragma unroll
            for (int hh = 0; hh < 2; hh++) {
                const int row = m1 + l4 + hh * 8;
                const float v0 = sc[nt][hh * 2 + 0] * scale;
                const float v1 = sc[nt][hh * 2 + 1] * scale;
                ss[row * ASS_STR + col]     = (col     < SV) ? v0 : -1e30f;
                ss[row * ASS_STR + col + 1] = (col + 1 < SV) ? v1 : -1e30f;
            }
        }
        __syncthreads();
        if (c + 2 < ANCH) att_load_kv(kg, c + 2, kb, tid);
        else CP_COMMIT();
    }

    att_load_kv(vg, 0, kvb, tid);
    att_load_kv(vg, 1, kvb + KVB, tid);

    // ================= softmax =================
#pragma unroll
    for (int i = 0; i < 8; i++) {
        const int r = w * 8 + i;
        float mx = -1e30f;
#pragma unroll
        for (int j = 0; j < 10; j++)
            mx = fmaxf(mx, ss[r * ASS_STR + lane + j * 32]);
#pragma unroll
        for (int o = 16; o; o >>= 1)
            mx = fmaxf(mx, __shfl_xor_sync(0xffffffffu, mx, o));
        float sum = 0.f;
        float ev[10];
#pragma unroll
        for (int j = 0; j < 10; j++) {
            ev[j] = expf(ss[r * ASS_STR + lane + j * 32] - mx);
            sum += ev[j];
        }
#pragma unroll
        for (int o = 16; o; o >>= 1)
            sum += __shfl_xor_sync(0xffffffffu, sum, o);
        const float inv = 1.f / sum;
#pragma unroll
        for (int j = 0; j < 10; j++)
            ah[r * (AHR / 2) + lane + j * 32] = __float2half_rn(ev[j] * inv);
    }

    // ================= pass 2: ctx = attn @ V =================
    const int m2  = (w & 1) * 32;
    const int n0w = (w >> 1) * 72;
    float ctx[2][9][4];
#pragma unroll
    for (int mt = 0; mt < 2; mt++)
#pragma unroll
        for (int nt = 0; nt < 9; nt++)
#pragma unroll
            for (int r = 0; r < 4; r++) ctx[mt][nt][r] = 0.f;

    for (int c = 0; c < ANCH; c++) {
        CP_WAIT(1);
        __syncthreads();
        const uint32_t vb = kvb + (c & 1) * KVB;

        uint32_t af2[2][2][4];
#pragma unroll
        for (int mt = 0; mt < 2; mt++) {
            const uint32_t abase = ahb + (m2 + mt * 16 + (lane & 15)) * AHR +
                                   (lane >> 4) * 16;
            ldsm_x4(af2[mt][0], abase + (2 * c) * 32);
            ldsm_x4(af2[mt][1], abase + (2 * c) * 32 + 32);
        }
#pragma unroll
        for (int kk = 0; kk < 2; kk++) {
#pragma unroll
            for (int p = 0; p < 5; p++) {
                uint32_t bfk[4];
                const uint32_t baddr = vb + (kk * 16 + (lane & 15)) * AQR +
                                       (n0w + p * 16 + (lane >> 4) * 8) * 2;
                ldsm_x4_t(bfk, baddr);
#pragma unroll
                for (int mt = 0; mt < 2; mt++) {
                    mma_f16(ctx[mt][2 * p], af2[mt][kk], &bfk[0]);
                    if (2 * p + 1 < 9)
                        mma_f16(ctx[mt][2 * p + 1], af2[mt][kk], &bfk[2]);
                }
            }
        }
        __syncthreads();
        if (c + 2 < ANCH) att_load_kv(vg, c + 2, vb, tid);
        else CP_COMMIT();
    }

#pragma unroll
    for (int mt = 0; mt < 2; mt++) {
#pragma unroll
        for (int hh = 0; hh < 2; hh++) {
            const int row = m2 + mt * 16 + l4 + hh * 8;
            __half* og = O + ((size_t)(b * SQ + q0 + row)) * DM + h * DK;
#pragma unroll
            for (int nt = 0; nt < 9; nt++) {
                const int col = n0w + nt * 8 + lk * 2;
                *(__half2*)(og + col) =
                    __floats2half2_rn(ctx[mt][nt][hh * 2 + 0],
                                      ctx[mt][nt][hh * 2 + 1]);
            }
        }
    }
}

// ---------------------------------------------------------------------------
// Orchestration (single stream — graph-safe, allocation-free)
// 4th launch = Q-GEMM (the ncu-profiled slot).
// ---------------------------------------------------------------------------
extern "C" void kernel_launch(void* const* d_in, const int* in_sizes, int n_in,
                              void* d_out, int out_size)
{
    const float* vision = (const float*)d_in[0];
    const float* text   = (const float*)d_in[1];
    const float* vp_w   = (const float*)d_in[2];
    const float* vp_b   = (const float*)d_in[3];
    const float* ln1_w  = (const float*)d_in[4];
    const float* ln1_b  = (const float*)d_in[5];
    const float* ln2_w  = (const float*)d_in[6];
    const float* ln2_b  = (const float*)d_in[7];
    const float* wq_w   = (const float*)d_in[8];
    const float* wq_b   = (const float*)d_in[9];
    const float* wk_w   = (const float*)d_in[10];
    const float* wk_b   = (const float*)d_in[11];
    const float* wv_w   = (const float*)d_in[12];
    const float* wv_b   = (const float*)d_in[13];
    const float* wo_w   = (const float*)d_in[14];
    const float* wo_b   = (const float*)d_in[15];
    const float* f1_w   = (const float*)d_in[16];
    const float* f1_b   = (const float*)d_in[17];
    const float* f2_w   = (const float*)d_in[18];
    const float* f2_b   = (const float*)d_in[19];
    float* out = (float*)d_out;

    float *x;
    __half *q, *kv, *pv, *nt, *ctx, *h, *vis, *w16;
    cudaGetSymbolAddress((void**)&x,   g_x);
    cudaGetSymbolAddress((void**)&q,   g_q);
    cudaGetSymbolAddress((void**)&kv,  g_kv);
    cudaGetSymbolAddress((void**)&pv,  g_pv);
    cudaGetSymbolAddress((void**)&nt,  g_nt);
    cudaGetSymbolAddress((void**)&ctx, g_ctx);
    cudaGetSymbolAddress((void**)&h,   g_h);
    cudaGetSymbolAddress((void**)&vis, g_vis);
    cudaGetSymbolAddress((void**)&w16, g_w16);

    const int SM64 = GC<64>::SMEM;   // 153600
    const int SM96 = GC<96>::SMEM;   // 227328
    cudaFuncSetAttribute(hgemm<0,1,64>, cudaFuncAttributeMaxDynamicSharedMemorySize, SM64);
    cudaFuncSetAttribute(hgemm<0,1,96>, cudaFuncAttributeMaxDynamicSharedMemorySize, SM96);
    cudaFuncSetAttribute(hgemm<1,0,96>, cudaFuncAttributeMaxDynamicSharedMemorySize, SM96);
    cudaFuncSetAttribute(hgemm<2,1,96>, cudaFuncAttributeMaxDynamicSharedMemorySize, SM96);
    cudaFuncSetAttribute(attention_kernel,
                         cudaFuncAttributeMaxDynamicSharedMemorySize, AT_SMEM);

    const dim3 blk(512);
    const int mtV = (ROWS_V + TM - 1) / TM;   // 17
    const int mtT = ROWS_T / TM;              // 128

    // 1. cvt wq  2. LN1  3. cvt vision  4. Q-GEMM (profiled)
    cvt16_kernel<<<2048, 256>>>((const float4*)wq_w, (uint2*)(w16 + OFF_WQ),
                                (size_t)DM * DM / 4);
    layernorm_kernel<<<ROWS_T, 256>>>(text, ln1_w, ln1_b, nt);
    cvt16_kernel<<<2048, 256>>>((const float4*)vision, (uint2*)vis,
                                (size_t)ROWS_V * DV / 4);
    hgemm<0,1,96><<<dim3(DM / TN, mtT), blk, SM96>>>(
        nt, w16 + OFF_WQ, wq_b, nullptr, 0, nullptr, q, ROWS_T, DM, DM);
    cvt16_kernel<<<2048, 256>>>((const float4*)vp_w, (uint2*)(w16 + OFF_VP),
                                (size_t)DV * DM / 4);
    hgemm<0,1,64><<<dim3(DM / TN, mtV), blk, SM64>>>(
        vis, w16 + OFF_VP, vp_b, nullptr, 0, nullptr, pv, ROWS_V, DM, DV);
    cvtkv_kernel<<<2048, 256>>>((const float4*)wk_w, (const float4*)wv_w,
                                (uint2*)(w16 + OFF_WK));
    hgemm<0,1,96><<<dim3((2 * DM) / TN, mtV), blk, SM96>>>(
        pv, w16 + OFF_WK, wk_b, wv_b, DM, nullptr, kv, ROWS_V, 2 * DM, DM);
    attention_kernel<<<dim3(SQ / ATQ, BATCH * NH), 256, AT_SMEM>>>(q, kv, ctx);
    cvt16_kernel<<<2048, 256>>>((const float4*)wo_w, (uint2*)(w16 + OFF_WO),
                                (size_t)DM * DM / 4);
    hgemm<1,0,96><<<dim3(DM / TN, mtT), blk, SM96>>>(
        ctx, w16 + OFF_WO, wo_b, nullptr, 0, text, x, ROWS_T, DM, DM);
    layernorm_kernel<<<ROWS_T, 256>>>(x, ln2_w, ln2_b, nt);
    cvt16_kernel<<<2048, 256>>>((const float4*)f1_w, (uint2*)(w16 + OFF_F1),
                                (size_t)DM * DF / 4);
    hgemm<2,1,96><<<dim3(DF / TN, mtT), blk, SM96>>>(
        nt, w16 + OFF_F1, f1_b, nullptr, 0, nullptr, h, ROWS_T, DF, DM);
    cvt16_kernel<<<2048, 256>>>((const float4*)f2_w, (uint2*)(w16 + OFF_F2),
                                (size_t)DF * DM / 4);
    hgemm<1,0,96><<<dim3(DM / TN, mtT), blk, SM96>>>(
        h, w16 + OFF_F2, f2_b, nullptr, 0, x, out, ROWS_T, DM, DF);
}